// round 15
// baseline (speedup 1.0000x reference)
#include <cuda_runtime.h>
#include <cuda_bf16.h>

#define B_    4096
#define DIN_  784
#define DZ_   128
#define T_    256
#define BZ_   (B_*DZ_)

// scratch: 1/rate per (b,z)   (device global — no allocation)
__device__ float g_inv_rate[BZ_];

typedef unsigned long long u64;

// packed fp32 FMA (sm_103a f32x2 pipe): d = a*b + d, lanewise on 2 floats
__device__ __forceinline__ void fma2(u64& d, u64 a, u64 b) {
    asm("fma.rn.f32x2 %0, %1, %2, %3;" : "=l"(d) : "l"(a), "l"(b), "l"(d));
}
__device__ __forceinline__ float lo32(u64 v) { return __uint_as_float((unsigned)(v & 0xffffffffu)); }
__device__ __forceinline__ float hi32(u64 v) { return __uint_as_float((unsigned)(v >> 32)); }

__device__ __forceinline__ float tanh_fast(float x) {
    float y; asm("tanh.approx.f32 %0, %1;" : "=f"(y) : "f"(x)); return y;
}

// ---------------------------------------------------------------------------
// GEMM geometry (enc & dec): BM=32, BN=64, BK=16, 256 threads.
// Micro-tile 2 rows x 4 cols per thread; cols as 2 f32x2 pairs.
// As_dup[k][2m] holds x[m][k] DUPLICATED {a,a} -> dup operand = 1 LDS.64.
// Bs[k][n] -> 1 LDS.128 gives 2 col-pairs. 7 issues per 8 FMAs.
// ---------------------------------------------------------------------------

// Kernel 1: du = min(x@W_enc + b_enc, 5); inv_rate = 1/(exp(min(du+min(prior,5),5))+1e-6)
// grid (B/32, DZ/64) = (128, 2);  784 = 49*16, no K tail.
__global__ void __launch_bounds__(256) enc_kernel(const float* __restrict__ x,
                                                  const float* __restrict__ W,
                                                  const float* __restrict__ bias,
                                                  const float* __restrict__ prior,
                                                  float* __restrict__ du_out) {
    __shared__ __align__(16) float As_dup[16][68];  // [k][2m(+dup)], 272B rows (16B-aligned)
    __shared__ __align__(16) float Bs[16][64];      // [k][n]
    const int tid  = threadIdx.x;
    const int bm   = blockIdx.x * 32;
    const int bn   = blockIdx.y * 64;
    const int row0 = (tid >> 4) * 2;   // 16 groups * 2 rows = 32
    const int col0 = (tid & 15) * 4;   // 16 groups * 4 cols = 64

    // loader indices
    const int lm = tid >> 3;           // 0..31  (m row)
    const int lk = (tid & 7) * 2;      // 0,2,..,14 (k pair)
    const int bkk = tid >> 4;          // 0..15  (B k-row)
    const int bn4 = (tid & 15) * 4;    // B col quad

    u64 acc[2][2] = {{0ull, 0ull}, {0ull, 0ull}};

    for (int k0 = 0; k0 < DIN_; k0 += 16) {
        // x tile: 32(m) x 16(k), 2 elems/thread, stored transposed+duplicated
        float2 xv = *(const float2*)(x + (size_t)(bm + lm) * DIN_ + k0 + lk);
        *(float2*)(&As_dup[lk    ][2 * lm]) = make_float2(xv.x, xv.x);
        *(float2*)(&As_dup[lk + 1][2 * lm]) = make_float2(xv.y, xv.y);
        // W tile: 16(k) x 64(n), 1 float4/thread
        *(float4*)(&Bs[bkk][bn4]) =
            *(const float4*)(W + (size_t)(k0 + bkk) * DZ_ + bn + bn4);
        __syncthreads();

        #pragma unroll
        for (int kk = 0; kk < 16; kk++) {
            u64 a0 = *(const u64*)(&As_dup[kk][2 * row0]);
            u64 a1 = *(const u64*)(&As_dup[kk][2 * (row0 + 1)]);
            float4 b4 = *(const float4*)(&Bs[kk][col0]);
            u64 b01 = *(const u64*)(&b4.x);
            u64 b23 = *(const u64*)(&b4.z);
            fma2(acc[0][0], a0, b01);
            fma2(acc[0][1], a0, b23);
            fma2(acc[1][0], a1, b01);
            fma2(acc[1][1], a1, b23);
        }
        __syncthreads();
    }

    #pragma unroll
    for (int i = 0; i < 2; i++) {
        int r = bm + row0 + i;
        float v[4] = { lo32(acc[i][0]), hi32(acc[i][0]), lo32(acc[i][1]), hi32(acc[i][1]) };
        #pragma unroll
        for (int j = 0; j < 4; j++) {
            int n = bn + col0 + j;
            float du = fminf(v[j] + bias[n], 5.0f);
            du_out[(size_t)r * DZ_ + n] = du;
            float lr = fminf(du + fminf(prior[n], 5.0f), 5.0f);
            float rate = __expf(lr) + 1e-6f;
            g_inv_rate[(size_t)r * DZ_ + n] = 1.0f / rate;
        }
    }
}

// ---------------------------------------------------------------------------
// Kernel 2: exponential race with monotone early exit; sigmoid via HW tanh.
//   sigmoid(1-t) = 0.5 - 0.5*tanh((t-1)/2).  Once all 32 lanes have t>16,
//   remaining terms < 3e-7 each -> tail bounded by ~8e-5 absolute.
// ---------------------------------------------------------------------------
__global__ void __launch_bounds__(256) race_kernel(const float* __restrict__ u,
                                                   float* __restrict__ z_out) {
    const int gid = blockIdx.x * 256 + threadIdx.x;   // 0..BZ_-1
    const float inv = g_inv_rate[gid];
    const float* up = u + gid;

    float times = 0.0f;
    float zacc  = 0.0f;

    for (int t = 0; t < T_; t += 8) {
        float uu[8];
        #pragma unroll
        for (int i = 0; i < 8; i++)
            uu[i] = __ldg(up + (size_t)(t + i) * BZ_);
        #pragma unroll
        for (int i = 0; i < 8; i++) {
            float e  = -__logf(1.0f - uu[i]);             // 1-u exact (Sterbenz)
            times    = fmaf(e, inv, times);
            float th = tanh_fast((times - 1.0f) * 0.5f);  // saturates cleanly
            zacc     = fmaf(-0.5f, th, zacc + 0.5f);      // += sigmoid(1-times)
        }
        if (__all_sync(0xffffffffu, times > 16.0f)) break;
    }
    z_out[gid] = zacc;
}

// ---------------------------------------------------------------------------
// Kernel 3: y = sigmoid(z@W_dec + b_dec)
// Same FFMA2 template. grid (128, 13); K=128=8*16; N-edge guarded (784).
// ---------------------------------------------------------------------------
__global__ void __launch_bounds__(256) dec_kernel(const float* __restrict__ z,
                                                  const float* __restrict__ W,
                                                  const float* __restrict__ bias,
                                                  float* __restrict__ y) {
    __shared__ __align__(16) float As_dup[16][68];
    __shared__ __align__(16) float Bs[16][64];
    const int tid  = threadIdx.x;
    const int bm   = blockIdx.x * 32;
    const int bn   = blockIdx.y * 64;
    const int row0 = (tid >> 4) * 2;
    const int col0 = (tid & 15) * 4;

    const int lm = tid >> 3;
    const int lk = (tid & 7) * 2;
    const int bkk = tid >> 4;
    const int bn4 = (tid & 15) * 4;

    u64 acc[2][2] = {{0ull, 0ull}, {0ull, 0ull}};

    for (int k0 = 0; k0 < DZ_; k0 += 16) {
        float2 zv = *(const float2*)(z + (size_t)(bm + lm) * DZ_ + k0 + lk);
        *(float2*)(&As_dup[lk    ][2 * lm]) = make_float2(zv.x, zv.x);
        *(float2*)(&As_dup[lk + 1][2 * lm]) = make_float2(zv.y, zv.y);

        int gn = bn + bn4;
        float4 wv = make_float4(0.f, 0.f, 0.f, 0.f);
        if (gn < DIN_)                     // 784 % 4 == 0 -> whole quad valid
            wv = *(const float4*)(W + (size_t)(k0 + bkk) * DIN_ + gn);
        *(float4*)(&Bs[bkk][bn4]) = wv;
        __syncthreads();

        #pragma unroll
        for (int kk = 0; kk < 16; kk++) {
            u64 a0 = *(const u64*)(&As_dup[kk][2 * row0]);
            u64 a1 = *(const u64*)(&As_dup[kk][2 * (row0 + 1)]);
            float4 b4 = *(const float4*)(&Bs[kk][col0]);
            u64 b01 = *(const u64*)(&b4.x);
            u64 b23 = *(const u64*)(&b4.z);
            fma2(acc[0][0], a0, b01);
            fma2(acc[0][1], a0, b23);
            fma2(acc[1][0], a1, b01);
            fma2(acc[1][1], a1, b23);
        }
        __syncthreads();
    }

    #pragma unroll
    for (int i = 0; i < 2; i++) {
        int r = bm + row0 + i;
        float v[4] = { lo32(acc[i][0]), hi32(acc[i][0]), lo32(acc[i][1]), hi32(acc[i][1]) };
        #pragma unroll
        for (int j = 0; j < 4; j++) {
            int gn = bn + col0 + j;
            if (gn < DIN_) {
                float s = v[j] + bias[gn];
                float ex = __expf(-s);
                y[(size_t)r * DIN_ + gn] = __fdividef(1.0f, 1.0f + ex);
            }
        }
    }
}

// ---------------------------------------------------------------------------
// launch — inputs: x, u, W_enc, b_enc, W_dec, b_dec, prior
// output: concat(du [B,DZ], z [B,DZ], y [B,DIN])
// ---------------------------------------------------------------------------
extern "C" void kernel_launch(void* const* d_in, const int* in_sizes, int n_in,
                              void* d_out, int out_size) {
    const float* x     = (const float*)d_in[0];
    const float* u     = (const float*)d_in[1];
    const float* W_enc = (const float*)d_in[2];
    const float* b_enc = (const float*)d_in[3];
    const float* W_dec = (const float*)d_in[4];
    const float* b_dec = (const float*)d_in[5];
    const float* prior = (const float*)d_in[6];

    float* out_du = (float*)d_out;
    float* out_z  = out_du + BZ_;
    float* out_y  = out_z  + BZ_;

    dim3 g1(B_ / 32, DZ_ / 64);
    enc_kernel<<<g1, 256>>>(x, W_enc, b_enc, prior, out_du);

    race_kernel<<<BZ_ / 256, 256>>>(u, out_z);

    dim3 g3(B_ / 32, (DIN_ + 63) / 64);
    dec_kernel<<<g3, 256>>>(out_z, W_dec, b_dec, out_y);
}

// round 17
// speedup vs baseline: 1.4700x; 1.4700x over previous
#include <cuda_runtime.h>
#include <cuda_bf16.h>

#define B_    4096
#define DIN_  784
#define DZ_   128
#define T_    256
#define BZ_   (B_*DZ_)

// scratch: 1/rate per (b,z)   (device global — no allocation)
__device__ float g_inv_rate[BZ_];

__device__ __forceinline__ float tanh_fast(float x) {
    float y; asm("tanh.approx.f32 %0, %1;" : "=f"(y) : "f"(x)); return y;
}

// ---------------------------------------------------------------------------
// GEMM geometry (R10 shape + double buffering):
//   BM=32, BN=64, BK=32, 128 threads, 4x4 micro-tile.
//   As[buf][k][m] padded rows of 36 (144B = 9*16B -> LDS.128 aligned)
//   Bs[buf][k][n] rows of 64.
//   Inner kk: 2x LDS.128 + 16 FFMA.  Register-staged prefetch of tile t+1
//   overlaps LDG latency with compute; ONE barrier per tile.
// ---------------------------------------------------------------------------

// Kernel 1: du = min(x@W_enc + b_enc, 5); inv_rate = 1/(exp(min(du+min(prior,5),5))+1e-6)
// grid (B/32, DZ/64) = (128, 2).  784 = 24*32 + 16 -> masked K-tail.
__global__ void __launch_bounds__(128) enc_kernel(const float* __restrict__ x,
                                                  const float* __restrict__ W,
                                                  const float* __restrict__ bias,
                                                  const float* __restrict__ prior,
                                                  float* __restrict__ du_out) {
    __shared__ __align__(16) float As[2][32][36];   // [buf][k][m]
    __shared__ __align__(16) float Bs[2][32][64];   // [buf][k][n]
    const int tid  = threadIdx.x;
    const int bm   = blockIdx.x * 32;
    const int bn   = blockIdx.y * 64;
    const int col0 = (tid & 15) * 4;
    const int row0 = (tid >> 4) * 4;

    // loader indices
    const int ar  = tid >> 3;          // 0..15 -> pairs of rows? no: x tile is 32(m) x 32(k)
    const int ac4 = (tid & 7) * 4;     // k quad within row
    const int bk0 = tid >> 4;          // 0..7  (B k-row base; +8 stride)
    const int bn4 = (tid & 15) * 4;    // B col quad

    const int NT = (DIN_ + 31) / 32;   // 25

    float4 ra[2];     // x stage: rows ar, ar+16
    float4 rb[4];     // W stage: k-rows bk0, bk0+8, bk0+16, bk0+24

    // ---- prefetch tile 0 ----
    {
        const int k0 = 0, krem = DIN_;
        #pragma unroll
        for (int j = 0; j < 2; j++) {
            int r = ar + j * 16;
            ra[j] = (ac4 < krem) ? *(const float4*)(x + (size_t)(bm + r) * DIN_ + k0 + ac4)
                                 : make_float4(0.f,0.f,0.f,0.f);
        }
        #pragma unroll
        for (int j = 0; j < 4; j++) {
            int kk = bk0 + j * 8;
            rb[j] = (kk < krem) ? *(const float4*)(W + (size_t)(k0 + kk) * DZ_ + bn + bn4)
                                : make_float4(0.f,0.f,0.f,0.f);
        }
    }

    float acc[4][4] = {};
    int buf = 0;

    for (int t = 0; t < NT; t++) {
        // ---- store staged regs into smem[buf] (A transposed to [k][m]) ----
        #pragma unroll
        for (int j = 0; j < 2; j++) {
            int r = ar + j * 16;
            As[buf][ac4    ][r] = ra[j].x;
            As[buf][ac4 + 1][r] = ra[j].y;
            As[buf][ac4 + 2][r] = ra[j].z;
            As[buf][ac4 + 3][r] = ra[j].w;
        }
        #pragma unroll
        for (int j = 0; j < 4; j++)
            *(float4*)(&Bs[buf][bk0 + j * 8][bn4]) = rb[j];
        __syncthreads();

        // ---- prefetch tile t+1 (LDG overlapped with compute below) ----
        if (t + 1 < NT) {
            const int k0 = (t + 1) * 32;
            const int krem = DIN_ - k0;            // multiple of 16 at tail
            #pragma unroll
            for (int j = 0; j < 2; j++) {
                int r = ar + j * 16;
                ra[j] = (ac4 < krem) ? *(const float4*)(x + (size_t)(bm + r) * DIN_ + k0 + ac4)
                                     : make_float4(0.f,0.f,0.f,0.f);
            }
            #pragma unroll
            for (int j = 0; j < 4; j++) {
                int kk = bk0 + j * 8;
                rb[j] = (kk < krem) ? *(const float4*)(W + (size_t)(k0 + kk) * DZ_ + bn + bn4)
                                    : make_float4(0.f,0.f,0.f,0.f);
            }
        }

        // ---- compute from smem[buf] ----
        #pragma unroll
        for (int kk = 0; kk < 32; kk++) {
            float4 a4 = *(const float4*)(&As[buf][kk][row0]);
            float4 b4 = *(const float4*)(&Bs[buf][kk][col0]);
            const float a[4] = {a4.x, a4.y, a4.z, a4.w};
            const float b[4] = {b4.x, b4.y, b4.z, b4.w};
            #pragma unroll
            for (int i = 0; i < 4; i++)
                #pragma unroll
                for (int j = 0; j < 4; j++)
                    acc[i][j] = fmaf(a[i], b[j], acc[i][j]);
        }
        buf ^= 1;
        // no second barrier: a warp storing tile t+1 passed sync(t), so every
        // warp has finished compute(t-1) — the only reader of that buffer.
    }

    #pragma unroll
    for (int i = 0; i < 4; i++) {
        int r = bm + row0 + i;
        #pragma unroll
        for (int j = 0; j < 4; j++) {
            int n = bn + col0 + j;
            float du = fminf(acc[i][j] + bias[n], 5.0f);
            du_out[(size_t)r * DZ_ + n] = du;
            float lr = fminf(du + fminf(prior[n], 5.0f), 5.0f);
            float rate = __expf(lr) + 1e-6f;
            g_inv_rate[(size_t)r * DZ_ + n] = 1.0f / rate;
        }
    }
}

// ---------------------------------------------------------------------------
// Kernel 2: exponential race, monotone early exit, HW-tanh sigmoid.
//   sigmoid(1-t) = 0.5 - 0.5*tanh((t-1)/2); once all 32 lanes have t>16 the
//   remaining terms are < 3e-7 each (tail < ~8e-5 absolute on z).
// ---------------------------------------------------------------------------
__global__ void __launch_bounds__(256) race_kernel(const float* __restrict__ u,
                                                   float* __restrict__ z_out) {
    const int gid = blockIdx.x * 256 + threadIdx.x;
    const float inv = g_inv_rate[gid];
    const float* up = u + gid;

    float times = 0.0f;
    float zacc  = 0.0f;

    for (int t = 0; t < T_; t += 8) {
        float uu[8];
        #pragma unroll
        for (int i = 0; i < 8; i++)
            uu[i] = __ldg(up + (size_t)(t + i) * BZ_);
        #pragma unroll
        for (int i = 0; i < 8; i++) {
            float e  = -__logf(1.0f - uu[i]);             // 1-u exact (Sterbenz)
            times    = fmaf(e, inv, times);
            float th = tanh_fast((times - 1.0f) * 0.5f);
            zacc     = fmaf(-0.5f, th, zacc + 0.5f);      // += sigmoid(1-times)
        }
        if (__all_sync(0xffffffffu, times > 16.0f)) break;
    }
    z_out[gid] = zacc;
}

// ---------------------------------------------------------------------------
// Kernel 3: y = sigmoid(z@W_dec + b_dec).  Same DB template; K=128 (4 tiles,
// no K-mask); N-edge guarded (784).  grid (128, 13).
// ---------------------------------------------------------------------------
__global__ void __launch_bounds__(128) dec_kernel(const float* __restrict__ z,
                                                  const float* __restrict__ W,
                                                  const float* __restrict__ bias,
                                                  float* __restrict__ y) {
    __shared__ __align__(16) float As[2][32][36];
    __shared__ __align__(16) float Bs[2][32][64];
    const int tid  = threadIdx.x;
    const int bm   = blockIdx.x * 32;
    const int bn   = blockIdx.y * 64;
    const int col0 = (tid & 15) * 4;
    const int row0 = (tid >> 4) * 4;

    const int ar  = tid >> 3;
    const int ac4 = (tid & 7) * 4;
    const int bk0 = tid >> 4;
    const int bn4 = (tid & 15) * 4;
    const bool bok = (bn + bn4) < DIN_;     // 784 % 4 == 0 -> whole quad valid

    const int NT = DZ_ / 32;                // 4

    float4 ra[2];
    float4 rb[4];

    {
        #pragma unroll
        for (int j = 0; j < 2; j++)
            ra[j] = *(const float4*)(z + (size_t)(bm + ar + j * 16) * DZ_ + ac4);
        #pragma unroll
        for (int j = 0; j < 4; j++)
            rb[j] = bok ? *(const float4*)(W + (size_t)(bk0 + j * 8) * DIN_ + bn + bn4)
                        : make_float4(0.f,0.f,0.f,0.f);
    }

    float acc[4][4] = {};
    int buf = 0;

    for (int t = 0; t < NT; t++) {
        #pragma unroll
        for (int j = 0; j < 2; j++) {
            int r = ar + j * 16;
            As[buf][ac4    ][r] = ra[j].x;
            As[buf][ac4 + 1][r] = ra[j].y;
            As[buf][ac4 + 2][r] = ra[j].z;
            As[buf][ac4 + 3][r] = ra[j].w;
        }
        #pragma unroll
        for (int j = 0; j < 4; j++)
            *(float4*)(&Bs[buf][bk0 + j * 8][bn4]) = rb[j];
        __syncthreads();

        if (t + 1 < NT) {
            const int k0 = (t + 1) * 32;
            #pragma unroll
            for (int j = 0; j < 2; j++)
                ra[j] = *(const float4*)(z + (size_t)(bm + ar + j * 16) * DZ_ + k0 + ac4);
            #pragma unroll
            for (int j = 0; j < 4; j++)
                rb[j] = bok ? *(const float4*)(W + (size_t)(k0 + bk0 + j * 8) * DIN_ + bn + bn4)
                            : make_float4(0.f,0.f,0.f,0.f);
        }

        #pragma unroll
        for (int kk = 0; kk < 32; kk++) {
            float4 a4 = *(const float4*)(&As[buf][kk][row0]);
            float4 b4 = *(const float4*)(&Bs[buf][kk][col0]);
            const float a[4] = {a4.x, a4.y, a4.z, a4.w};
            const float b[4] = {b4.x, b4.y, b4.z, b4.w};
            #pragma unroll
            for (int i = 0; i < 4; i++)
                #pragma unroll
                for (int j = 0; j < 4; j++)
                    acc[i][j] = fmaf(a[i], b[j], acc[i][j]);
        }
        buf ^= 1;
    }

    #pragma unroll
    for (int i = 0; i < 4; i++) {
        int r = bm + row0 + i;
        #pragma unroll
        for (int j = 0; j < 4; j++) {
            int gn = bn + col0 + j;
            if (gn < DIN_) {
                float s = acc[i][j] + bias[gn];
                float ex = __expf(-s);
                y[(size_t)r * DIN_ + gn] = __fdividef(1.0f, 1.0f + ex);
            }
        }
    }
}

// ---------------------------------------------------------------------------
// launch — inputs: x, u, W_enc, b_enc, W_dec, b_dec, prior
// output: concat(du [B,DZ], z [B,DZ], y [B,DIN])
// ---------------------------------------------------------------------------
extern "C" void kernel_launch(void* const* d_in, const int* in_sizes, int n_in,
                              void* d_out, int out_size) {
    const float* x     = (const float*)d_in[0];
    const float* u     = (const float*)d_in[1];
    const float* W_enc = (const float*)d_in[2];
    const float* b_enc = (const float*)d_in[3];
    const float* W_dec = (const float*)d_in[4];
    const float* b_dec = (const float*)d_in[5];
    const float* prior = (const float*)d_in[6];

    float* out_du = (float*)d_out;
    float* out_z  = out_du + BZ_;
    float* out_y  = out_z  + BZ_;

    dim3 g1(B_ / 32, DZ_ / 64);
    enc_kernel<<<g1, 128>>>(x, W_enc, b_enc, prior, out_du);

    race_kernel<<<BZ_ / 256, 256>>>(u, out_z);

    dim3 g3(B_ / 32, (DIN_ + 63) / 64);
    dec_kernel<<<g3, 128>>>(out_z, W_dec, b_dec, out_y);
}